// round 6
// baseline (speedup 1.0000x reference)
#include <cuda_runtime.h>
#include <cuda_bf16.h>
#include <math.h>
#include <stdint.h>

// ---------------- problem constants (fixed shapes) ----------------
#define N_NODES 131072
#define EDIM    64
#define L0      262144
#define L1      524288
#define L2      393216
#define NROWS   (L0 + L1 + L2)   // 1179648
#define SCAN_BLOCKS 512

typedef __nv_bfloat16 bf16;

// ---------------- scratch (device globals; no cudaMalloc allowed) ----------
__device__ float g_msg[(size_t)NROWS * EDIM];     // node-sorted message rows
__device__ float g_mf [(size_t)N_NODES * EDIM];   // max_msg per node
__device__ int   g_idx[NROWS];
__device__ int   g_cnt[N_NODES];                  // zero at load; reduce re-zeroes
__device__ int   g_start[N_NODES];
__device__ int   g_rank[N_NODES];
__device__ int   g_flag[N_NODES];                 // zero at load; reduce re-zeroes
__device__ int   g_bsum[SCAN_BLOCKS];
__device__ int   g_mode;

// ---------------- helpers ----------------
__device__ __forceinline__ float mishf(float x) {
    float sp = (x > 20.0f) ? x : log1pf(expf(x));
    return x * tanhf(sp);
}
__device__ __forceinline__ uint32_t smaddr(const void* p) {
    return (uint32_t)__cvta_generic_to_shared(p);
}
__device__ __forceinline__ void ldsm_x4(uint32_t a, uint32_t r[4]) {
    asm volatile("ldmatrix.sync.aligned.m8n8.x4.shared.b16 {%0,%1,%2,%3}, [%4];"
                 : "=r"(r[0]), "=r"(r[1]), "=r"(r[2]), "=r"(r[3]) : "r"(a));
}
__device__ __forceinline__ void ldsm_x4t(uint32_t a, uint32_t r[4]) {
    asm volatile("ldmatrix.sync.aligned.m8n8.x4.trans.shared.b16 {%0,%1,%2,%3}, [%4];"
                 : "=r"(r[0]), "=r"(r[1]), "=r"(r[2]), "=r"(r[3]) : "r"(a));
}
__device__ __forceinline__ void mma16816(float c[4], const uint32_t a[4],
                                         uint32_t b0, uint32_t b1) {
    asm volatile("mma.sync.aligned.m16n8k16.row.col.f32.bf16.bf16.f32 "
                 "{%0,%1,%2,%3}, {%4,%5,%6,%7}, {%8,%9}, {%0,%1,%2,%3};"
                 : "+f"(c[0]), "+f"(c[1]), "+f"(c[2]), "+f"(c[3])
                 : "r"(a[0]), "r"(a[1]), "r"(a[2]), "r"(a[3]), "r"(b0), "r"(b1));
}
// split two fp32 into packed bf16 (hi-part pair, lo-part pair)
__device__ __forceinline__ void split2pack(float x0, float x1, uint32_t& hp, uint32_t& lp) {
    bf16 h0 = __float2bfloat16_rn(x0);
    bf16 h1 = __float2bfloat16_rn(x1);
    bf16 l0 = __float2bfloat16_rn(x0 - __bfloat162float(h0));
    bf16 l1 = __float2bfloat16_rn(x1 - __bfloat162float(h1));
    hp = (uint32_t)__bfloat16_as_ushort(h0) | ((uint32_t)__bfloat16_as_ushort(h1) << 16);
    lp = (uint32_t)__bfloat16_as_ushort(l0) | ((uint32_t)__bfloat16_as_ushort(l1) << 16);
}

// ---------------- 1. index dtype detection ----------------
__global__ void detect_kernel(const unsigned* __restrict__ p) {
    __shared__ unsigned red[256];
    unsigned v = 0;
    for (int i = threadIdx.x; i < 4096; i += 256) v |= p[2 * i + 1];
    red[threadIdx.x] = v;
    __syncthreads();
    for (int s = 128; s > 0; s >>= 1) {
        if (threadIdx.x < s) red[threadIdx.x] |= red[threadIdx.x + s];
        __syncthreads();
    }
    if (threadIdx.x == 0) g_mode = (red[0] != 0) ? 1 : 0;
}

// ---------------- 2. convert + histogram + rel0 flag ----------------
__global__ void convhist_kernel(const void* __restrict__ p0,
                                const void* __restrict__ p1,
                                const void* __restrict__ p2) {
    int i = blockIdx.x * 256 + threadIdx.x;
    if (i >= NROWS) return;
    const void* p; int o;
    if      (i < L0)      { p = p0; o = i; }
    else if (i < L0 + L1) { p = p1; o = i - L0; }
    else                  { p = p2; o = i - L0 - L1; }
    int v;
    if (g_mode) v = ((const int*)p)[o];
    else        v = (int)(((const long long*)p)[o]);
    g_idx[i] = v;
    atomicAdd(&g_cnt[v], 1);
    if (i < L0) g_flag[v] = 1;
}

// ---------------- 3. hierarchical exclusive scan ----------------
__global__ void scanA_kernel() {
    __shared__ int wsum[8];
    const int t = threadIdx.x;
    int v = g_cnt[blockIdx.x * 256 + t];
#pragma unroll
    for (int s = 16; s > 0; s >>= 1) v += __shfl_down_sync(0xffffffffu, v, s);
    if ((t & 31) == 0) wsum[t >> 5] = v;
    __syncthreads();
    if (t < 8) {
        int x = wsum[t];
#pragma unroll
        for (int s = 4; s > 0; s >>= 1) x += __shfl_down_sync(0xffu, x, s);
        if (t == 0) g_bsum[blockIdx.x] = x;
    }
}
__global__ void scanB_kernel() {
    __shared__ int wsum[16];
    const int t = threadIdx.x;
    const int lane = t & 31, w = t >> 5;
    int v = g_bsum[t];
    int inc = v;
#pragma unroll
    for (int s = 1; s < 32; s <<= 1) {
        int u = __shfl_up_sync(0xffffffffu, inc, s);
        if (lane >= s) inc += u;
    }
    if (lane == 31) wsum[w] = inc;
    __syncthreads();
    if (t < 16) {
        int x = wsum[t];
#pragma unroll
        for (int s = 1; s < 16; s <<= 1) {
            int u = __shfl_up_sync(0xffffu, x, s);
            if (t >= s) x += u;
        }
        wsum[t] = x;
    }
    __syncthreads();
    int wofs = (w == 0) ? 0 : wsum[w - 1];
    g_bsum[t] = wofs + inc - v;
}
__global__ void scanC_kernel() {
    __shared__ int wsum[8];
    const int t = threadIdx.x;
    const int lane = t & 31, w = t >> 5;
    const int i = blockIdx.x * 256 + t;
    int v = g_cnt[i];
    int inc = v;
#pragma unroll
    for (int s = 1; s < 32; s <<= 1) {
        int u = __shfl_up_sync(0xffffffffu, inc, s);
        if (lane >= s) inc += u;
    }
    if (lane == 31) wsum[w] = inc;
    __syncthreads();
    if (t < 8) {
        int x = wsum[t];
#pragma unroll
        for (int s = 1; s < 8; s <<= 1) {
            int u = __shfl_up_sync(0xffu, x, s);
            if (t >= s) x += u;
        }
        wsum[t] = x;
    }
    __syncthreads();
    int wofs = (w == 0) ? 0 : wsum[w - 1];
    g_start[i] = g_bsum[blockIdx.x] + wofs + inc - v;
    g_rank[i]  = 0;
}

// ---------------- n-chunk accumulation core (64 output cols) ---------------
template <int D>
__device__ __forceinline__ void nchunk_accum(
    float acc[8][4],
    const bf16* __restrict__ Ab0, const bf16* __restrict__ Ab1,
    bf16* wb0, bf16* wb1,
    const float* __restrict__ Wg, int n0, int Ntot)
{
    const int tid = threadIdx.x, w = tid >> 5, lane = tid & 31;
    const int AS = D + 8, WS = 72;
    for (int k0 = 0; k0 < D; k0 += 32) {
        __syncthreads();
        // stage + split W[k0..k0+31][n0..n0+63]
        for (int i = tid; i < 32 * 32; i += 128) {
            int kr = i >> 5, cp = (i & 31) * 2;
            float2 v = *(const float2*)&Wg[(size_t)(k0 + kr) * Ntot + n0 + cp];
            uint32_t hp, lp;
            split2pack(v.x, v.y, hp, lp);
            *(uint32_t*)&wb0[kr * WS + cp] = hp;
            *(uint32_t*)&wb1[kr * WS + cp] = lp;
        }
        __syncthreads();
#pragma unroll
        for (int k16 = 0; k16 < 32; k16 += 16) {
            uint32_t a0[4], a1[4];
            const int arow = (w * 16 + (lane & 15)) * AS + k0 + k16 + (lane >> 4) * 8;
            ldsm_x4(smaddr(&Ab0[arow]), a0);
            ldsm_x4(smaddr(&Ab1[arow]), a1);
#pragma unroll
            for (int n16 = 0; n16 < 4; ++n16) {
                uint32_t b0[4], b1[4];
                const int bofs = (k16 + (lane & 15)) * WS + n16 * 16 + (lane >> 4) * 8;
                ldsm_x4t(smaddr(&wb0[bofs]), b0);
                ldsm_x4t(smaddr(&wb1[bofs]), b1);
                mma16816(acc[n16 * 2 + 0], a0, b0[0], b0[1]);
                mma16816(acc[n16 * 2 + 1], a0, b0[2], b0[3]);
                mma16816(acc[n16 * 2 + 0], a0, b1[0], b1[1]);
                mma16816(acc[n16 * 2 + 1], a0, b1[2], b1[3]);
                mma16816(acc[n16 * 2 + 0], a1, b0[0], b0[1]);
                mma16816(acc[n16 * 2 + 1], a1, b0[2], b0[3]);
            }
        }
    }
}

// ---------------- per-relation gather + MLP + sorted store (tensor core) ---
template <int D, int A>
__global__ __launch_bounds__(128) void msg_mma_kernel(
    const float* __restrict__ emb,
    const float* __restrict__ Wr, const float* __restrict__ rb,
    const float* __restrict__ Wo, const float* __restrict__ ob,
    int idx_ofs)
{
    extern __shared__ __align__(16) char smraw[];
    const int AS = D + 8, WS = 72;
    bf16* xb0 = (bf16*)smraw;
    bf16* xb1 = xb0 + 64 * AS;
    bf16* zb0 = xb1 + 64 * AS;
    bf16* zb1 = zb0 + 64 * AS;
    bf16* wb0 = zb1 + 64 * AS;
    bf16* wb1 = wb0 + 32 * WS;
    float* biasS = (float*)(wb1 + 32 * WS);   // [2*D]
    int*   idxS  = (int*)(biasS + 2 * D);     // [64*A]
    int*   posS  = idxS + 64 * A;             // [64*A]

    const int tid = threadIdx.x, w = tid >> 5, lane = tid & 31;
    const int gid = lane >> 2, cbase = (lane & 3) * 2;
    const int t0 = blockIdx.x * 64;

    // preload indices, fused rank (segment order is arbitrary), biases
    for (int i = tid; i < 64 * A; i += 128) {
        int node = g_idx[idx_ofs + t0 * A + i];
        idxS[i] = node;
        posS[i] = g_start[node] + atomicAdd(&g_rank[node], 1);
    }
    for (int i = tid; i < D; i += 128) { biasS[i] = rb[i]; biasS[D + i] = ob[i]; }
    __syncthreads();   // idxS/biasS written by other threads — required

    // gather + split input rows: x[r][col] = emb[node(r, col>>6)*64 + (col&63)]
    for (int i = tid; i < 64 * (D / 4); i += 128) {
        int r = i / (D / 4), c4 = i % (D / 4);
        int col = c4 * 4, j = col >> 6;
        int node = idxS[r * A + j];
        float4 v = *(const float4*)&emb[(size_t)node * EDIM + (col & 63)];
        uint32_t h0, l0, h1, l1;
        split2pack(v.x, v.y, h0, l0);
        split2pack(v.z, v.w, h1, l1);
        *(uint2*)&xb0[r * AS + col] = make_uint2(h0, h1);
        *(uint2*)&xb1[r * AS + col] = make_uint2(l0, l1);
    }

    // ---- GEMM1: h = x @ rw + rb ; z = x + mish(h) ----
    for (int n0 = 0; n0 < D; n0 += 64) {
        float acc[8][4];
#pragma unroll
        for (int nt = 0; nt < 8; ++nt) {
            float b0 = biasS[n0 + nt * 8 + cbase];
            float b1 = biasS[n0 + nt * 8 + cbase + 1];
            acc[nt][0] = b0; acc[nt][1] = b1; acc[nt][2] = b0; acc[nt][3] = b1;
        }
        nchunk_accum<D>(acc, xb0, xb1, wb0, wb1, Wr, n0, D);
#pragma unroll
        for (int nt = 0; nt < 8; ++nt) {
            int colp = n0 + nt * 8 + cbase;
#pragma unroll
            for (int h = 0; h < 2; ++h) {
                int row = w * 16 + gid + h * 8;
                uint32_t xh = *(const uint32_t*)&xb0[row * AS + colp];
                uint32_t xl = *(const uint32_t*)&xb1[row * AS + colp];
                float x0 = __uint_as_float((xh & 0xffffu) << 16) +
                           __uint_as_float((xl & 0xffffu) << 16);
                float x1 = __uint_as_float(xh & 0xffff0000u) +
                           __uint_as_float(xl & 0xffff0000u);
                float z0 = x0 + mishf(acc[nt][h * 2 + 0]);
                float z1 = x1 + mishf(acc[nt][h * 2 + 1]);
                uint32_t zh, zl;
                split2pack(z0, z1, zh, zl);
                *(uint32_t*)&zb0[row * AS + colp] = zh;
                *(uint32_t*)&zb1[row * AS + colp] = zl;
            }
        }
    }

    // ---- GEMM2: out = z @ ow + ob ; scatter to node-sorted slots ----
    for (int n0 = 0; n0 < D; n0 += 64) {
        float acc[8][4];
#pragma unroll
        for (int nt = 0; nt < 8; ++nt) {
            float b0 = biasS[D + n0 + nt * 8 + cbase];
            float b1 = biasS[D + n0 + nt * 8 + cbase + 1];
            acc[nt][0] = b0; acc[nt][1] = b1; acc[nt][2] = b0; acc[nt][3] = b1;
        }
        nchunk_accum<D>(acc, zb0, zb1, wb0, wb1, Wo, n0, D);
#pragma unroll
        for (int nt = 0; nt < 8; ++nt) {
            int colp = n0 + nt * 8 + cbase;
            int j = colp >> 6, e = colp & 63;
#pragma unroll
            for (int h = 0; h < 2; ++h) {
                int row = w * 16 + gid + h * 8;
                int p = posS[row * A + j];
                float2 v = make_float2(acc[nt][h * 2 + 0], acc[nt][h * 2 + 1]);
                *(float2*)&g_msg[(size_t)p * EDIM + e] = v;
            }
        }
    }
}

// ---------------- segment softmax-reduce ----------------
__global__ void reduce_kernel() {
    int node = (blockIdx.x * blockDim.x + threadIdx.x) >> 5;
    if (node >= N_NODES) return;
    const int lane  = threadIdx.x & 31;
    const int start = g_start[node];
    const int end   = start + g_cnt[node];
    const float base = g_flag[node] ? -INFINITY : 0.0f;

    float m0 = base, m1 = base;
    for (int r = start; r < end; ++r) {
        const float* row = &g_msg[(size_t)r * EDIM];
        m0 = fmaxf(m0, row[lane]);
        m1 = fmaxf(m1, row[lane + 32]);
    }
    float s0 = 1e-16f, s1 = 1e-16f;
    for (int r = start; r < end; ++r) {
        const float* row = &g_msg[(size_t)r * EDIM];
        s0 += expf(12.0f * (row[lane]      - m0));
        s1 += expf(12.0f * (row[lane + 32] - m1));
    }
    size_t o = (size_t)node * EDIM;
    g_mf[o + lane]      = logf(s0) * (1.0f / 12.0f) + m0;
    g_mf[o + lane + 32] = logf(s1) * (1.0f / 12.0f) + m1;
    if (lane == 0) { g_cnt[node] = 0; g_flag[node] = 0; }   // ready for next replay
}

// ---------------- node update MLP (tensor core): [mf|emb](128) -> 64 -------
__global__ __launch_bounds__(128) void update_mma_kernel(
    const float* __restrict__ emb,
    const float* __restrict__ Wr, const float* __restrict__ rb,
    const float* __restrict__ Wo, const float* __restrict__ ob,
    float* __restrict__ out)
{
    extern __shared__ __align__(16) char smraw[];
    const int AS = 136, WS = 72;   // K = 128
    bf16* xb0 = (bf16*)smraw;
    bf16* xb1 = xb0 + 64 * AS;
    bf16* zb0 = xb1 + 64 * AS;
    bf16* zb1 = zb0 + 64 * AS;
    bf16* wb0 = zb1 + 64 * AS;
    bf16* wb1 = wb0 + 32 * WS;
    float* biasS = (float*)(wb1 + 32 * WS);   // [128 + 64]

    const int tid = threadIdx.x, w = tid >> 5, lane = tid & 31;
    const int gid = lane >> 2, cbase = (lane & 3) * 2;
    const int n0g = blockIdx.x * 64;

    for (int i = tid; i < 128; i += 128) biasS[i] = rb[i];
    if (tid < 64) biasS[128 + tid] = ob[tid];

    // gather [mf | emb]
    for (int i = tid; i < 64 * 32; i += 128) {
        int r = i >> 5, c4 = i & 31;
        int col = c4 * 4;
        const float* src = (col < 64)
            ? &g_mf[(size_t)(n0g + r) * EDIM + col]
            : &emb[(size_t)(n0g + r) * EDIM + col - 64];
        float4 v = *(const float4*)src;
        uint32_t h0, l0, h1, l1;
        split2pack(v.x, v.y, h0, l0);
        split2pack(v.z, v.w, h1, l1);
        *(uint2*)&xb0[r * AS + col] = make_uint2(h0, h1);
        *(uint2*)&xb1[r * AS + col] = make_uint2(l0, l1);
    }
    __syncthreads();   // biasS/xb written by other threads — required

    // GEMM1: K=128, N=128
    for (int n0 = 0; n0 < 128; n0 += 64) {
        float acc[8][4];
#pragma unroll
        for (int nt = 0; nt < 8; ++nt) {
            float b0 = biasS[n0 + nt * 8 + cbase];
            float b1 = biasS[n0 + nt * 8 + cbase + 1];
            acc[nt][0] = b0; acc[nt][1] = b1; acc[nt][2] = b0; acc[nt][3] = b1;
        }
        nchunk_accum<128>(acc, xb0, xb1, wb0, wb1, Wr, n0, 128);
#pragma unroll
        for (int nt = 0; nt < 8; ++nt) {
            int colp = n0 + nt * 8 + cbase;
#pragma unroll
            for (int h = 0; h < 2; ++h) {
                int row = w * 16 + gid + h * 8;
                uint32_t xh = *(const uint32_t*)&xb0[row * AS + colp];
                uint32_t xl = *(const uint32_t*)&xb1[row * AS + colp];
                float x0 = __uint_as_float((xh & 0xffffu) << 16) +
                           __uint_as_float((xl & 0xffffu) << 16);
                float x1 = __uint_as_float(xh & 0xffff0000u) +
                           __uint_as_float(xl & 0xffff0000u);
                float z0 = x0 + mishf(acc[nt][h * 2 + 0]);
                float z1 = x1 + mishf(acc[nt][h * 2 + 1]);
                uint32_t zh, zl;
                split2pack(z0, z1, zh, zl);
                *(uint32_t*)&zb0[row * AS + colp] = zh;
                *(uint32_t*)&zb1[row * AS + colp] = zl;
            }
        }
    }

    // GEMM2: K=128, N=64
    {
        float acc[8][4];
#pragma unroll
        for (int nt = 0; nt < 8; ++nt) {
            float b0 = biasS[128 + nt * 8 + cbase];
            float b1 = biasS[128 + nt * 8 + cbase + 1];
            acc[nt][0] = b0; acc[nt][1] = b1; acc[nt][2] = b0; acc[nt][3] = b1;
        }
        nchunk_accum<128>(acc, zb0, zb1, wb0, wb1, Wo, 0, 64);
#pragma unroll
        for (int nt = 0; nt < 8; ++nt) {
            int colp = nt * 8 + cbase;
#pragma unroll
            for (int h = 0; h < 2; ++h) {
                int row = w * 16 + gid + h * 8;
                float2 v = make_float2(acc[nt][h * 2 + 0], acc[nt][h * 2 + 1]);
                *(float2*)&out[(size_t)(n0g + row) * EDIM + colp] = v;
            }
        }
    }
}

// ---------------- launcher ----------------
extern "C" void kernel_launch(void* const* d_in, const int* in_sizes, int n_in,
                              void* d_out, int out_size) {
    const float* emb = (const float*)d_in[0];
    const void*  i0  = d_in[1];
    const void*  i1  = d_in[2];
    const void*  i2  = d_in[3];
    const float* r0rw = (const float*)d_in[4];
    const float* r0rb = (const float*)d_in[5];
    const float* r0ow = (const float*)d_in[6];
    const float* r0ob = (const float*)d_in[7];
    const float* r1rw = (const float*)d_in[8];
    const float* r1rb = (const float*)d_in[9];
    const float* r1ow = (const float*)d_in[10];
    const float* r1ob = (const float*)d_in[11];
    const float* r2rw = (const float*)d_in[12];
    const float* r2rb = (const float*)d_in[13];
    const float* r2ow = (const float*)d_in[14];
    const float* r2ob = (const float*)d_in[15];
    const float* urw  = (const float*)d_in[16];
    const float* urb  = (const float*)d_in[17];
    const float* uow  = (const float*)d_in[18];
    const float* uob  = (const float*)d_in[19];
    float* out = (float*)d_out;

    const int SM64  = 512 * 72  + 9216 + 8 * 64  + 512 * 1;   // 47104
    const int SM128 = 512 * 136 + 9216 + 8 * 128 + 512 * 2;   // 80896
    const int SM192 = 512 * 200 + 9216 + 8 * 192 + 512 * 3;   // 114688
    const int SMUPD = 512 * 136 + 9216 + 4 * 192;             // 79616
    cudaFuncSetAttribute(msg_mma_kernel< 64, 1>, cudaFuncAttributeMaxDynamicSharedMemorySize, SM64);
    cudaFuncSetAttribute(msg_mma_kernel<128, 2>, cudaFuncAttributeMaxDynamicSharedMemorySize, SM128);
    cudaFuncSetAttribute(msg_mma_kernel<192, 3>, cudaFuncAttributeMaxDynamicSharedMemorySize, SM192);
    cudaFuncSetAttribute(update_mma_kernel,      cudaFuncAttributeMaxDynamicSharedMemorySize, SMUPD);

    // prelude: launches 1-5
    detect_kernel<<<1, 256>>>((const unsigned*)i0);
    convhist_kernel<<<(NROWS + 255) / 256, 256>>>(i0, i1, i2);
    scanA_kernel<<<SCAN_BLOCKS, 256>>>();
    scanB_kernel<<<1, SCAN_BLOCKS>>>();
    scanC_kernel<<<SCAN_BLOCKS, 256>>>();

    // launch 6 = biggest GEMM (lands under ncu -s 5 -c 1)
    msg_mma_kernel<128, 2><<<(L1 / 2) / 64, 128, SM128>>>(emb, r1rw, r1rb, r1ow, r1ob, L0);
    msg_mma_kernel< 64, 1><<<(L0 / 1) / 64, 128, SM64 >>>(emb, r0rw, r0rb, r0ow, r0ob, 0);
    msg_mma_kernel<192, 3><<<(L2 / 3) / 64, 128, SM192>>>(emb, r2rw, r2rb, r2ow, r2ob, L0 + L1);

    reduce_kernel<<<(N_NODES * 32 + 255) / 256, 256>>>();
    update_mma_kernel<<<N_NODES / 64, 128, SMUPD>>>(emb, urw, urb, uow, uob, out);
}

// round 7
// speedup vs baseline: 1.2189x; 1.2189x over previous
#include <cuda_runtime.h>
#include <math.h>
#include <stdint.h>

// ---------------- problem constants (fixed shapes) ----------------
#define N_NODES 131072
#define EDIM    64
#define L0      262144
#define L1      524288
#define L2      393216
#define NROWS   (L0 + L1 + L2)   // 1179648
#define SCAN_BLOCKS 512          // N_NODES / 256

// ---------------- scratch (device globals; no cudaMalloc allowed) ----------
__device__ float g_msg[(size_t)NROWS * EDIM];     // node-sorted message rows
__device__ float g_mf [(size_t)N_NODES * EDIM];   // final max_msg per node
__device__ int   g_idx[NROWS];
__device__ int   g_cnt[N_NODES];                  // zero at load; reduce re-zeroes
__device__ int   g_start[N_NODES];
__device__ int   g_rank[N_NODES];                 // zeroed by scanBC each run
__device__ int   g_flag[N_NODES];                 // zero at load; reduce re-zeroes
__device__ int   g_bsum[SCAN_BLOCKS];

// ---------------- helpers ----------------
__device__ __forceinline__ float mishf(float x) {
    float sp = (x > 20.0f) ? x : log1pf(expf(x));
    return x * tanhf(sp);
}

// ---- packed f32x2 FMA (ptxas never emits FFMA2 from C++; PTX-only) ----
typedef unsigned long long ull;
__device__ __forceinline__ ull dup2(float w) {
    ull d;
    asm("mov.b64 %0, {%1, %1};" : "=l"(d) : "f"(w));
    return d;
}
__device__ __forceinline__ void fma2(ull& acc, ull x, ull w) {
    asm("fma.rn.f32x2 %0, %1, %2, %3;" : "=l"(acc) : "l"(x), "l"(w), "l"(acc));
}
__device__ __forceinline__ void unpack2(ull v, float& lo, float& hi) {
    asm("mov.b64 {%0, %1}, %2;" : "=f"(lo), "=f"(hi) : "l"(v));
}

// ---------------- 1. convert + histogram + rel0 flag (inline dtype detect) -
// Genuine int64 (values < 2^31): odd 32-bit words are zero. Each block checks
// 16 odd words of rel0_idx (same 128B for all blocks -> L2 broadcast).
__global__ void convhist_kernel(const void* __restrict__ p0,
                                const void* __restrict__ p1,
                                const void* __restrict__ p2) {
    __shared__ int modeS;
    if (threadIdx.x < 32) {
        unsigned v = 0;
        if (threadIdx.x < 16) v = ((const unsigned*)p0)[threadIdx.x * 2 + 1];
        unsigned any = __ballot_sync(0xffffffffu, v != 0);
        if (threadIdx.x == 0) modeS = any ? 1 : 0;   // 1 = int32 data
    }
    __syncthreads();
    const int mode = modeS;

    int i = blockIdx.x * 256 + threadIdx.x;
    if (i >= NROWS) return;
    const void* p; int o;
    if      (i < L0)      { p = p0; o = i; }
    else if (i < L0 + L1) { p = p1; o = i - L0; }
    else                  { p = p2; o = i - L0 - L1; }
    int v;
    if (mode) v = ((const int*)p)[o];
    else      v = (int)(((const long long*)p)[o]);
    g_idx[i] = v;
    atomicAdd(&g_cnt[v], 1);
    if (i < L0) g_flag[v] = 1;   // racy identical writes: benign
}

// ---------------- 2a. per-block (256 nodes) sums ----------------
__global__ void scanA_kernel() {
    __shared__ int wsum[8];
    const int t = threadIdx.x;
    int v = g_cnt[blockIdx.x * 256 + t];
#pragma unroll
    for (int s = 16; s > 0; s >>= 1) v += __shfl_down_sync(0xffffffffu, v, s);
    if ((t & 31) == 0) wsum[t >> 5] = v;
    __syncthreads();
    if (t < 8) {
        int x = wsum[t];
#pragma unroll
        for (int s = 4; s > 0; s >>= 1) x += __shfl_down_sync(0xffu, x, s);
        if (t == 0) g_bsum[blockIdx.x] = x;
    }
}

// ---------------- 2b. base offset (masked reduce) + local scan --------------
__global__ void scanBC_kernel() {
    __shared__ int wsum[8];
    __shared__ int baseS;
    const int t = threadIdx.x;
    const int lane = t & 31, w = t >> 5;
    const int b = blockIdx.x;

    // base = sum of g_bsum[j] for j < b   (each thread covers 2 entries)
    {
        int j0 = 2 * t, j1 = 2 * t + 1;
        int v = ((j0 < b) ? g_bsum[j0] : 0) + ((j1 < b) ? g_bsum[j1] : 0);
#pragma unroll
        for (int s = 16; s > 0; s >>= 1) v += __shfl_down_sync(0xffffffffu, v, s);
        if (lane == 0) wsum[w] = v;
        __syncthreads();
        if (t < 8) {
            int x = wsum[t];
#pragma unroll
            for (int s = 4; s > 0; s >>= 1) x += __shfl_down_sync(0xffu, x, s);
            if (t == 0) baseS = x;
        }
        __syncthreads();
    }

    // local exclusive scan of this block's 256 counts
    const int i = b * 256 + t;
    int v = g_cnt[i];
    int inc = v;
#pragma unroll
    for (int s = 1; s < 32; s <<= 1) {
        int u = __shfl_up_sync(0xffffffffu, inc, s);
        if (lane >= s) inc += u;
    }
    __syncthreads();             // wsum reuse
    if (lane == 31) wsum[w] = inc;
    __syncthreads();
    if (t < 8) {
        int x = wsum[t];
#pragma unroll
        for (int s = 1; s < 8; s <<= 1) {
            int u = __shfl_up_sync(0xffu, x, s);
            if (t >= s) x += u;
        }
        wsum[t] = x;
    }
    __syncthreads();
    int wofs = (w == 0) ? 0 : wsum[w - 1];
    g_start[i] = baseS + wofs + inc - v;
    g_rank[i]  = 0;
}

// ---------------- 3. per-relation fused gather + MLP + sorted store --------
// blockDim.x == D (one thread per column), R tuples per block.
// Row pairs packed into f32x2 lanes: xs[p][2k+h] = element k of rows (2p,2p+1).
// Rank fused: slot = g_start[node] + atomicAdd(&g_rank[node],1)  (order-free).
template <int D, int A, int R>
__global__ void msg_kernel(const float* __restrict__ emb,
                           const float* __restrict__ rw, const float* __restrict__ rb,
                           const float* __restrict__ ow, const float* __restrict__ ob,
                           int idx_ofs) {
    constexpr int R2 = R / 2;
    __shared__ __align__(16) float xs[R2][2 * D];
    __shared__ __align__(16) float zs[R2][2 * D];
    __shared__ int idxS[R * A];
    __shared__ int posS[R * A];
    const int c  = threadIdx.x;          // column 0..D-1
    const int j  = c >> 6;               // which index within tuple
    const int e  = c & 63;
    const int t0 = blockIdx.x * R;

    // one thread per message row: node + fused rank
    if (c < R * A) {
        int node = g_idx[idx_ofs + t0 * A + c];
        idxS[c] = node;
        posS[c] = g_start[node] + atomicAdd(&g_rank[node], 1);
    }
    __syncthreads();

    float xreg[R];
    int   pos[R];
#pragma unroll
    for (int r = 0; r < R; ++r) {
        int node = idxS[r * A + j];
        pos[r]   = posS[r * A + j];
        xreg[r]  = emb[(size_t)node * EDIM + e];
        xs[r >> 1][2 * c + (r & 1)] = xreg[r];
    }
    __syncthreads();

    ull acc[R2];
    // ---- h = x @ rw + rb ----
#pragma unroll
    for (int p = 0; p < R2; ++p) acc[p] = dup2(rb[c]);
#pragma unroll 4
    for (int k = 0; k < D; k += 2) {
        ull w0 = dup2(rw[(k + 0) * D + c]);
        ull w1 = dup2(rw[(k + 1) * D + c]);
#pragma unroll
        for (int p = 0; p < R2; ++p) {
            ulonglong2 x2 = *reinterpret_cast<const ulonglong2*>(&xs[p][2 * k]);
            fma2(acc[p], x2.x, w0);
            fma2(acc[p], x2.y, w1);
        }
    }
    // ---- z = x + mish(h) ----
#pragma unroll
    for (int p = 0; p < R2; ++p) {
        float h0, h1;
        unpack2(acc[p], h0, h1);
        zs[p][2 * c + 0] = xreg[2 * p + 0] + mishf(h0);
        zs[p][2 * c + 1] = xreg[2 * p + 1] + mishf(h1);
    }
    __syncthreads();

    // ---- out = z @ ow + ob ----
#pragma unroll
    for (int p = 0; p < R2; ++p) acc[p] = dup2(ob[c]);
#pragma unroll 4
    for (int k = 0; k < D; k += 2) {
        ull w0 = dup2(ow[(k + 0) * D + c]);
        ull w1 = dup2(ow[(k + 1) * D + c]);
#pragma unroll
        for (int p = 0; p < R2; ++p) {
            ulonglong2 z2 = *reinterpret_cast<const ulonglong2*>(&zs[p][2 * k]);
            fma2(acc[p], z2.x, w0);
            fma2(acc[p], z2.y, w1);
        }
    }

    // ---- store message rows at node-sorted slots (no heavy atomics) ----
#pragma unroll
    for (int p = 0; p < R2; ++p) {
        float o0, o1;
        unpack2(acc[p], o0, o1);
        g_msg[(size_t)pos[2 * p + 0] * EDIM + e] = o0;
        g_msg[(size_t)pos[2 * p + 1] * EDIM + e] = o1;
    }
}

// ---------------- 4. segment softmax-reduce (single pass, online) ----------
// One warp per node; lane handles columns (lane, lane+32).
__global__ void reduce_kernel() {
    int node = (blockIdx.x * blockDim.x + threadIdx.x) >> 5;
    if (node >= N_NODES) return;
    const int lane  = threadIdx.x & 31;
    const int start = g_start[node];
    const int end   = start + g_cnt[node];
    const float base = g_flag[node] ? -INFINITY : 0.0f;

    float m0 = base, m1 = base;
    float s0 = 0.0f, s1 = 0.0f;
    for (int r = start; r < end; ++r) {
        const float* row = &g_msg[(size_t)r * EDIM];
        float v0 = row[lane], v1 = row[lane + 32];
        float n0 = fmaxf(m0, v0), n1 = fmaxf(m1, v1);
        s0 = s0 * expf(12.0f * (m0 - n0)) + expf(12.0f * (v0 - n0));
        s1 = s1 * expf(12.0f * (m1 - n1)) + expf(12.0f * (v1 - n1));
        m0 = n0; m1 = n1;
    }
    s0 += 1e-16f; s1 += 1e-16f;
    size_t o = (size_t)node * EDIM;
    g_mf[o + lane]      = logf(s0) * (1.0f / 12.0f) + m0;
    g_mf[o + lane + 32] = logf(s1) * (1.0f / 12.0f) + m1;
    if (lane == 0) { g_cnt[node] = 0; g_flag[node] = 0; }   // ready for next replay
}

// ---------------- 5. node update MLP: [max_msg | emb] (128) -> 64 ----------
template <int R>
__global__ void update_kernel(const float* __restrict__ emb,
                              const float* __restrict__ rw, const float* __restrict__ rb,
                              const float* __restrict__ ow, const float* __restrict__ ob,
                              float* __restrict__ out) {
    constexpr int R2 = R / 2;
    __shared__ __align__(16) float xs[R2][256];
    __shared__ __align__(16) float zs[R2][256];
    const int c  = threadIdx.x;     // 0..127
    const int n0 = blockIdx.x * R;

    float xreg[R];
#pragma unroll
    for (int r = 0; r < R; ++r) {
        int node = n0 + r;
        float v = (c < 64) ? g_mf[(size_t)node * EDIM + c]
                           : emb[(size_t)node * EDIM + (c - 64)];
        xreg[r] = v;
        xs[r >> 1][2 * c + (r & 1)] = v;
    }
    __syncthreads();

    ull acc[R2];
#pragma unroll
    for (int p = 0; p < R2; ++p) acc[p] = dup2(rb[c]);
#pragma unroll 4
    for (int k = 0; k < 128; k += 2) {
        ull w0 = dup2(rw[(k + 0) * 128 + c]);
        ull w1 = dup2(rw[(k + 1) * 128 + c]);
#pragma unroll
        for (int p = 0; p < R2; ++p) {
            ulonglong2 x2 = *reinterpret_cast<const ulonglong2*>(&xs[p][2 * k]);
            fma2(acc[p], x2.x, w0);
            fma2(acc[p], x2.y, w1);
        }
    }
#pragma unroll
    for (int p = 0; p < R2; ++p) {
        float h0, h1;
        unpack2(acc[p], h0, h1);
        zs[p][2 * c + 0] = xreg[2 * p + 0] + mishf(h0);
        zs[p][2 * c + 1] = xreg[2 * p + 1] + mishf(h1);
    }
    __syncthreads();

    const int cc = c & 63;
#pragma unroll
    for (int t = 0; t < 4; ++t) {
        int p = (c >> 6) + 2 * t;
        ull a = dup2(ob[cc]);
#pragma unroll 4
        for (int k = 0; k < 128; k += 2) {
            ull w0 = dup2(ow[(k + 0) * 64 + cc]);
            ull w1 = dup2(ow[(k + 1) * 64 + cc]);
            ulonglong2 z2 = *reinterpret_cast<const ulonglong2*>(&zs[p][2 * k]);
            fma2(a, z2.x, w0);
            fma2(a, z2.y, w1);
        }
        float o0, o1;
        unpack2(a, o0, o1);
        out[(size_t)(n0 + 2 * p + 0) * EDIM + cc] = o0;
        out[(size_t)(n0 + 2 * p + 1) * EDIM + cc] = o1;
    }
}

// ---------------- launcher ----------------
extern "C" void kernel_launch(void* const* d_in, const int* in_sizes, int n_in,
                              void* d_out, int out_size) {
    const float* emb = (const float*)d_in[0];
    const void*  i0  = d_in[1];
    const void*  i1  = d_in[2];
    const void*  i2  = d_in[3];
    const float* r0rw = (const float*)d_in[4];
    const float* r0rb = (const float*)d_in[5];
    const float* r0ow = (const float*)d_in[6];
    const float* r0ob = (const float*)d_in[7];
    const float* r1rw = (const float*)d_in[8];
    const float* r1rb = (const float*)d_in[9];
    const float* r1ow = (const float*)d_in[10];
    const float* r1ob = (const float*)d_in[11];
    const float* r2rw = (const float*)d_in[12];
    const float* r2rb = (const float*)d_in[13];
    const float* r2ow = (const float*)d_in[14];
    const float* r2ob = (const float*)d_in[15];
    const float* urw  = (const float*)d_in[16];
    const float* urb  = (const float*)d_in[17];
    const float* uow  = (const float*)d_in[18];
    const float* uob  = (const float*)d_in[19];
    float* out = (float*)d_out;

    // prelude (3 launches)
    convhist_kernel<<<(NROWS + 255) / 256, 256>>>(i0, i1, i2);
    scanA_kernel<<<SCAN_BLOCKS, 256>>>();
    scanBC_kernel<<<SCAN_BLOCKS, 256>>>();

    // launch #4 = msg<128> (lands in the ncu capture window)
    msg_kernel<128, 2, 16><<<(L1 / 2) / 16, 128>>>(emb, r1rw, r1rb, r1ow, r1ob, L0);
    msg_kernel< 64, 1, 16><<<(L0 / 1) / 16,  64>>>(emb, r0rw, r0rb, r0ow, r0ob, 0);
    msg_kernel<192, 3, 16><<<(L2 / 3) / 16, 192>>>(emb, r2rw, r2rb, r2ow, r2ob, L0 + L1);

    // single-pass segment softmax-reduce, then node update
    reduce_kernel<<<(N_NODES * 32 + 255) / 256, 256>>>();
    update_kernel<16><<<N_NODES / 16, 128>>>(emb, urw, urb, uow, uob, out);
}